// round 6
// baseline (speedup 1.0000x reference)
#include <cuda_runtime.h>
#include <cuda_bf16.h>
#include <cstdint>

#define B_   256
#define T_   512
#define H_   512
#define OUTC 1536

#define NCTA 128
#define NTHR 512

#define WSTRIDE 1168            // 576*2 + 16 pad -> ldmatrix conflict-free
#define OFF_WHI  0
#define OFF_WLO  74752          // 64*1168
#define OFF_A0   149504         // A chunk: [hi 8192 | lo 8192]
#define OFF_A1   165888
#define OFF_BIAS 182272
#define SMEM_BYTES 182528

// ---------------- persistent device scratch ----------------
__device__ unsigned short g_hb[2][2][B_ * H_];             // [parity][hi/lo][b*512+j]
__device__ unsigned short g_x2[2][(size_t)B_ * T_ * 64];   // [hi/lo][b][t][f]
__device__ float g_hf[H_ * B_];                            // final h, [j*256+b]
__device__ unsigned g_cnt[4 * 32];
__device__ volatile unsigned g_gen[4 * 32];

// ---------------- helpers ----------------
__device__ __forceinline__ uint32_t smem_u32(const void* p) {
    uint32_t a;
    asm("{ .reg .u64 t; cvta.to.shared.u64 t, %1; cvt.u32.u64 %0, t; }" : "=r"(a) : "l"(p));
    return a;
}
__device__ __forceinline__ void split1(float v, unsigned short& hi, unsigned short& lo) {
    __nv_bfloat16 h = __float2bfloat16_rn(v);
    float rem = v - __bfloat162float(h);
    hi = __bfloat16_as_ushort(h);
    lo = __bfloat16_as_ushort(__float2bfloat16_rn(rem));
}
__device__ __forceinline__ float sigm(float x) {
    return __fdividef(1.0f, 1.0f + __expf(-x));
}
__device__ __forceinline__ float tanh_(float x) {
    float e = __expf(2.0f * x);
    return 1.0f - __fdividef(2.0f, e + 1.0f);
}
__device__ __forceinline__ void cpa(uint32_t dst, const void* src) {
    asm volatile("cp.async.cg.shared.global [%0], [%1], 16;" :: "r"(dst), "l"(src) : "memory");
}
__device__ __forceinline__ void cpa_commit() { asm volatile("cp.async.commit_group;" ::: "memory"); }
__device__ __forceinline__ void cpa_wait()   { asm volatile("cp.async.wait_group 0;" ::: "memory"); }

__device__ __forceinline__ void ldsm4(uint32_t* r, uint32_t a) {
    asm volatile("ldmatrix.sync.aligned.m8n8.x4.shared.b16 {%0,%1,%2,%3}, [%4];"
                 : "=r"(r[0]), "=r"(r[1]), "=r"(r[2]), "=r"(r[3]) : "r"(a));
}
__device__ __forceinline__ void mma16816(float* c, const uint32_t* a, uint32_t b0, uint32_t b1) {
    asm volatile(
        "mma.sync.aligned.m16n8k16.row.col.f32.bf16.bf16.f32 "
        "{%0,%1,%2,%3}, {%4,%5,%6,%7}, {%8,%9}, {%0,%1,%2,%3};"
        : "+f"(c[0]), "+f"(c[1]), "+f"(c[2]), "+f"(c[3])
        : "r"(a[0]), "r"(a[1]), "r"(a[2]), "r"(a[3]), "r"(b0), "r"(b1));
}

// group barrier across the 32 CTAs of one batch group
__device__ __forceinline__ void gbar(int gb) {
    __threadfence();
    __syncthreads();
    if (threadIdx.x == 0) {
        volatile unsigned* gp = &g_gen[gb * 32];
        unsigned g = *gp;
        if (atomicAdd(&g_cnt[gb * 32], 1u) == 31u) {
            atomicExch(&g_cnt[gb * 32], 0u);
            __threadfence();
            *gp = g + 1u;
        } else {
            while (*gp == g) { }
        }
        __threadfence();
    }
    __syncthreads();
}

// ============ x prep: fp32 -> split bf16 (same [b][t][f] layout) ============
extern "C" __global__ void xsplit(const float* __restrict__ x) {
    size_t i = ((size_t)blockIdx.x * 256 + threadIdx.x) * 4;
    float4 v = __ldg((const float4*)(x + i));
    unsigned short h0, l0, h1, l1, h2, l2, h3, l3;
    split1(v.x, h0, l0); split1(v.y, h1, l1);
    split1(v.z, h2, l2); split1(v.w, h3, l3);
    ushort4 H = {h0, h1, h2, h3}, L = {l0, l1, l2, l3};
    *(ushort4*)(&g_x2[0][i]) = H;
    *(ushort4*)(&g_x2[1][i]) = L;
}

// ============ main persistent kernel ============
extern "C" __global__ void __launch_bounds__(NTHR, 1)
lstm_mma(const float* __restrict__ x,    const float* __restrict__ W_ih,
         const float* __restrict__ W_hh, const float* __restrict__ b_ih,
         const float* __restrict__ b_hh, const float* __restrict__ W_fc,
         const float* __restrict__ b_fc, float* __restrict__ out)
{
    extern __shared__ unsigned char smc[];
    const uint32_t sa = smem_u32(smc);
    const int tid = threadIdx.x, lane = tid & 31, w = tid >> 5;
    const int gb = blockIdx.x >> 5, ht = blockIdx.x & 31;
    const int wm = w & 3, wn = w >> 2;              // 4 M-tiles x 4 N-tiles of 16x16
    float* bs = (float*)(smc + OFF_BIAS);

    // ---- W split -> SMEM: row n (= jj*4+gate), k-major, stride 1168B
    for (int idx = tid; idx < 64 * 576; idx += NTHR) {
        int k = idx >> 6, n = idx & 63;
        int row = (n & 3) * 512 + ht * 16 + (n >> 2);
        float v = (k < 512) ? W_hh[(size_t)row * 512 + k] : W_ih[(size_t)row * 64 + (k - 512)];
        unsigned short hi, lo;
        split1(v, hi, lo);
        *(unsigned short*)(smc + OFF_WHI + n * WSTRIDE + k * 2) = hi;
        *(unsigned short*)(smc + OFF_WLO + n * WSTRIDE + k * 2) = lo;
    }
    if (tid < 64) {
        int row = (tid & 3) * 512 + ht * 16 + (tid >> 2);
        bs[tid] = b_ih[row] + b_hh[row];
    }
    // zero h parity-0 for this CTA's (b,j) block
    if (tid < 128) {
        int r = tid >> 1, hh = tid & 1;
        uint4 z = make_uint4(0, 0, 0, 0);
        *(uint4*)(&g_hb[0][0][(size_t)(gb * 64 + r) * 512 + ht * 16 + hh * 8]) = z;
        *(uint4*)(&g_hb[0][1][(size_t)(gb * 64 + r) * 512 + ht * 16 + hh * 8]) = z;
    }

    // staging indices: 512 threads, 1x 16B per plane per thread
    const int sr = tid >> 3;                 // row 0..63
    const int su = tid & 7;                  // 16B unit in row
    const uint32_t doff = (uint32_t)sr * 128 + (((uint32_t)su * 16) ^ ((uint32_t)(sr & 7) << 4));

    // prefetch x(t=0) into A0 (independent of h)
    {
        size_t o = ((size_t)(gb * 64 + sr) * T_ + 0) * 64 + su * 8;
        cpa(sa + OFF_A0 + doff, &g_x2[0][o]);
        cpa(sa + OFF_A0 + 8192 + doff, &g_x2[1][o]);
        cpa_commit();
    }
    gbar(gb);

    // per-lane address components (identical mapping to the verified R5 kernel)
    const int rowl = lane & 15;
    const uint32_t xm = (uint32_t)(lane & 7) << 4;        // A swizzle mask
    const uint32_t kl = (uint32_t)(lane >> 4) * 16;       // A k-half (bytes)
    const int nloc = wn * 16 + (lane & 7) + ((lane >> 4) << 3);
    const uint32_t krel = (uint32_t)((lane >> 3) & 1) * 16;
    const uint32_t bBaseHi = sa + OFF_WHI + (uint32_t)nloc * WSTRIDE + krel;
    const uint32_t bBaseLo = sa + OFF_WLO + (uint32_t)nloc * WSTRIDE + krel;
    const uint32_t aRow0 = (uint32_t)(wm * 16 + rowl) * 128;

    const int q = lane & 3, mth = q & 1;
    float cst[2] = {0.f, 0.f};

    for (int t = 0; t < T_; t++) {
        const int par = t & 1, nb = par ^ 1;

        cpa_wait();            // x chunk (prefetched pre-barrier) landed
        __syncthreads();

        float accm[2][4], accc[2][4];
        #pragma unroll
        for (int hf = 0; hf < 2; hf++)
            #pragma unroll
            for (int k2 = 0; k2 < 4; k2++) { accm[hf][k2] = 0.f; accc[hf][k2] = 0.f; }

        // chunk 0 = x (A0, W k-offset 1024B); chunks 1..8 = h 0..7 (alternating A1/A0)
        for (int ch = 0; ch < 9; ch++) {
            if (ch < 8) {      // prefetch h chunk 'ch' into the other buffer
                uint32_t d0 = sa + (((ch + 1) & 1) ? OFF_A1 : OFF_A0);
                size_t o = (size_t)(gb * 64 + sr) * 512 + ch * 64 + su * 8;
                cpa(d0 + doff, &g_hb[par][0][o]);
                cpa(d0 + 8192 + doff, &g_hb[par][1][o]);
                cpa_commit();
            }

            const uint32_t aB = sa + ((ch & 1) ? OFF_A1 : OFF_A0);
            const uint32_t bK = (ch == 0) ? 1024u : (uint32_t)(ch - 1) * 128u;
            #pragma unroll
            for (int kt = 0; kt < 4; kt++) {
                uint32_t kq = (((uint32_t)kt * 32) + kl) ^ xm;
                uint32_t hi[4], lo[4], bh[4], bl[4];
                ldsm4(hi, aB + aRow0 + kq);
                ldsm4(lo, aB + 8192 + aRow0 + kq);
                ldsm4(bh, bBaseHi + bK + kt * 32);
                ldsm4(bl, bBaseLo + bK + kt * 32);
                // 4 independent chains: accm[0], accm[1], accc[0], accc[1]
                mma16816(accm[0], hi, bh[0], bh[1]);
                mma16816(accm[1], hi, bh[2], bh[3]);
                mma16816(accc[0], hi, bl[0], bl[1]);
                mma16816(accc[1], hi, bl[2], bl[3]);
                mma16816(accc[0], lo, bh[0], bh[1]);
                mma16816(accc[1], lo, bh[2], bh[3]);
            }
            if (ch < 8) { cpa_wait(); __syncthreads(); }
        }

        __syncthreads();       // all warps done reading A0 (chunk 8)
        // prefetch next step's x into A0 (overlaps epilogue + barrier)
        {
            int tn = (t + 1) & (T_ - 1);
            size_t o = ((size_t)(gb * 64 + sr) * T_ + tn) * 64 + su * 8;
            cpa(sa + OFF_A0 + doff, &g_x2[0][o]);
            cpa(sa + OFF_A0 + 8192 + doff, &g_x2[1][o]);
            cpa_commit();
        }

        // ---- epilogue: combine acc, pair-exchange, gates, state update
        float cmb[2][4];
        #pragma unroll
        for (int hf = 0; hf < 2; hf++)
            #pragma unroll
            for (int k2 = 0; k2 < 4; k2++) cmb[hf][k2] = accm[hf][k2] + accc[hf][k2];

        float recv[2][2];
        #pragma unroll
        for (int hf = 0; hf < 2; hf++) {
            float s0 = mth ? cmb[hf][0] : cmb[hf][2];
            float s1 = mth ? cmb[hf][1] : cmb[hf][3];
            recv[hf][0] = __shfl_xor_sync(0xffffffffu, s0, 1);
            recv[hf][1] = __shfl_xor_sync(0xffffffffu, s1, 1);
        }
        const int rown = wm * 16 + (lane >> 2) + mth * 8;
        const int b = gb * 64 + rown;
        #pragma unroll
        for (int hf = 0; hf < 2; hf++) {
            int jj = wn * 4 + (q >> 1) + hf * 2;
            float I, F, G, O;
            if (mth == 0) { I = cmb[hf][0]; F = cmb[hf][1]; G = recv[hf][0]; O = recv[hf][1]; }
            else          { G = cmb[hf][2]; O = cmb[hf][3]; I = recv[hf][0]; F = recv[hf][1]; }
            I += bs[jj * 4 + 0]; F += bs[jj * 4 + 1];
            G += bs[jj * 4 + 2]; O += bs[jj * 4 + 3];
            float iv = sigm(I), fv = sigm(F), gv = tanh_(G), ov = sigm(O);
            float cv = fv * cst[hf] + iv * gv;
            cst[hf] = cv;
            float ho = ov * tanh_(cv);
            unsigned short hi, lo;
            split1(ho, hi, lo);
            int j = ht * 16 + jj;
            size_t o = (size_t)b * 512 + j;
            g_hb[nb][0][o] = hi;
            g_hb[nb][1][o] = lo;
            if (t == T_ - 1) g_hf[(size_t)j * 256 + b] = ho;
        }
        gbar(gb);
    }

    // ================= FC head =================
    float* smf = (float*)smc;
    for (int idx = tid; idx < (H_ * 64) / 4; idx += NTHR) {
        int jj2 = idx >> 4, qv = idx & 15;
        *(float4*)(smf + jj2 * 64 + qv * 4) =
            __ldcg((const float4*)(g_hf + (size_t)jj2 * 256 + gb * 64 + qv * 4));
    }
    __syncthreads();

    const int tx2 = tid & 15, ty2 = tid >> 4;      // 16 batch-quads x 32 row slots
    #pragma unroll
    for (int rr = 0; rr < 2; rr++) {
        int rl = rr * 32 + ty2;
        if (rl < 48) {
            int r = ht * 48 + rl;
            const float4* wr = (const float4*)(W_fc + (size_t)r * H_);
            float a0, a1, a2, a3;
            a0 = a1 = a2 = a3 = b_fc[r];
            #pragma unroll 4
            for (int j4 = 0; j4 < H_ / 4; j4++) {
                float4 w4 = __ldg(wr + j4);
                float4 h0 = *(const float4*)(smf + (j4 * 4 + 0) * 64 + tx2 * 4);
                float4 h1 = *(const float4*)(smf + (j4 * 4 + 1) * 64 + tx2 * 4);
                float4 h2 = *(const float4*)(smf + (j4 * 4 + 2) * 64 + tx2 * 4);
                float4 h3 = *(const float4*)(smf + (j4 * 4 + 3) * 64 + tx2 * 4);
                a0 += h0.x * w4.x + h1.x * w4.y + h2.x * w4.z + h3.x * w4.w;
                a1 += h0.y * w4.x + h1.y * w4.y + h2.y * w4.z + h3.y * w4.w;
                a2 += h0.z * w4.x + h1.z * w4.y + h2.z * w4.z + h3.z * w4.w;
                a3 += h0.w * w4.x + h1.w * w4.y + h2.w * w4.z + h3.w * w4.w;
            }
            int bbase = gb * 64 + tx2 * 4;
            out[(size_t)(bbase + 0) * OUTC + r] = a0;
            out[(size_t)(bbase + 1) * OUTC + r] = a1;
            out[(size_t)(bbase + 2) * OUTC + r] = a2;
            out[(size_t)(bbase + 3) * OUTC + r] = a3;
        }
    }
}

extern "C" void kernel_launch(void* const* d_in, const int* in_sizes, int n_in,
                              void* d_out, int out_size) {
    const float* x    = (const float*)d_in[0];
    const float* W_ih = (const float*)d_in[1];
    const float* W_hh = (const float*)d_in[2];
    const float* b_ih = (const float*)d_in[3];
    const float* b_hh = (const float*)d_in[4];
    const float* W_fc = (const float*)d_in[5];
    const float* b_fc = (const float*)d_in[6];
    float* out = (float*)d_out;

    xsplit<<<8192, 256>>>(x);
    cudaFuncSetAttribute(lstm_mma, cudaFuncAttributeMaxDynamicSharedMemorySize, SMEM_BYTES);
    lstm_mma<<<NCTA, NTHR, SMEM_BYTES>>>(x, W_ih, W_hh, b_ih, b_hh, W_fc, b_fc, out);
}

// round 7
// speedup vs baseline: 1.4519x; 1.4519x over previous
#include <cuda_runtime.h>
#include <cuda_bf16.h>
#include <cstdint>

#define B_   256
#define T_   512
#define H_   512
#define OUTC 1536

#define NCTA 128
#define NTHR 256

#define WSTRIDE 1168            // 576*2 + 16 pad -> ldmatrix conflict-free
#define OFF_WHI  0
#define OFF_WLO  74752          // 64*1168
#define OFF_A    149504         // 4 ring buffers x 16384 ([hi 8192 | lo 8192])
#define OFF_BIAS 215040
#define SMEM_BYTES 215296

// ---------------- persistent device scratch ----------------
__device__ unsigned short g_hb[2][2][B_ * H_];             // [parity][hi/lo][b*512+j]
__device__ unsigned short g_x2[2][(size_t)B_ * T_ * 64];   // [hi/lo][b][t][f]
__device__ float g_hf[H_ * B_];                            // final h, [j*256+b]
__device__ unsigned g_cnt[4 * 32];
__device__ volatile unsigned g_gen[4 * 32];

// ---------------- helpers ----------------
__device__ __forceinline__ uint32_t smem_u32(const void* p) {
    uint32_t a;
    asm("{ .reg .u64 t; cvta.to.shared.u64 t, %1; cvt.u32.u64 %0, t; }" : "=r"(a) : "l"(p));
    return a;
}
__device__ __forceinline__ void split1(float v, unsigned short& hi, unsigned short& lo) {
    __nv_bfloat16 h = __float2bfloat16_rn(v);
    float rem = v - __bfloat162float(h);
    hi = __bfloat16_as_ushort(h);
    lo = __bfloat16_as_ushort(__float2bfloat16_rn(rem));
}
__device__ __forceinline__ float sigm(float x) {
    return __fdividef(1.0f, 1.0f + __expf(-x));
}
__device__ __forceinline__ float tanh_(float x) {
    float e = __expf(2.0f * x);
    return 1.0f - __fdividef(2.0f, e + 1.0f);
}
__device__ __forceinline__ void cpa(uint32_t dst, const void* src) {
    asm volatile("cp.async.cg.shared.global [%0], [%1], 16;" :: "r"(dst), "l"(src) : "memory");
}
__device__ __forceinline__ void cpa_commit() { asm volatile("cp.async.commit_group;" ::: "memory"); }
__device__ __forceinline__ void cpa_wait0()  { asm volatile("cp.async.wait_group 0;" ::: "memory"); }
__device__ __forceinline__ void cpa_wait1()  { asm volatile("cp.async.wait_group 1;" ::: "memory"); }
__device__ __forceinline__ void cpa_wait2()  { asm volatile("cp.async.wait_group 2;" ::: "memory"); }

__device__ __forceinline__ void ldsm4(uint32_t* r, uint32_t a) {
    asm volatile("ldmatrix.sync.aligned.m8n8.x4.shared.b16 {%0,%1,%2,%3}, [%4];"
                 : "=r"(r[0]), "=r"(r[1]), "=r"(r[2]), "=r"(r[3]) : "r"(a));
}
__device__ __forceinline__ void mma16816(float* c, const uint32_t* a, uint32_t b0, uint32_t b1) {
    asm volatile(
        "mma.sync.aligned.m16n8k16.row.col.f32.bf16.bf16.f32 "
        "{%0,%1,%2,%3}, {%4,%5,%6,%7}, {%8,%9}, {%0,%1,%2,%3};"
        : "+f"(c[0]), "+f"(c[1]), "+f"(c[2]), "+f"(c[3])
        : "r"(a[0]), "r"(a[1]), "r"(a[2]), "r"(a[3]), "r"(b0), "r"(b1));
}

// group barrier across the 32 CTAs of one batch group
__device__ __forceinline__ void gbar(int gb) {
    __threadfence();
    __syncthreads();
    if (threadIdx.x == 0) {
        volatile unsigned* gp = &g_gen[gb * 32];
        unsigned g = *gp;
        if (atomicAdd(&g_cnt[gb * 32], 1u) == 31u) {
            atomicExch(&g_cnt[gb * 32], 0u);
            __threadfence();
            *gp = g + 1u;
        } else {
            while (*gp == g) { }
        }
        __threadfence();
    }
    __syncthreads();
}

// ============ x prep: fp32 -> split bf16 (same [b][t][f] layout) ============
extern "C" __global__ void xsplit(const float* __restrict__ x) {
    size_t i = ((size_t)blockIdx.x * 256 + threadIdx.x) * 4;
    float4 v = __ldg((const float4*)(x + i));
    unsigned short h0, l0, h1, l1, h2, l2, h3, l3;
    split1(v.x, h0, l0); split1(v.y, h1, l1);
    split1(v.z, h2, l2); split1(v.w, h3, l3);
    ushort4 H = {h0, h1, h2, h3}, L = {l0, l1, l2, l3};
    *(ushort4*)(&g_x2[0][i]) = H;
    *(ushort4*)(&g_x2[1][i]) = L;
}

// ============ main persistent kernel ============
extern "C" __global__ void __launch_bounds__(NTHR, 1)
lstm_mma(const float* __restrict__ x,    const float* __restrict__ W_ih,
         const float* __restrict__ W_hh, const float* __restrict__ b_ih,
         const float* __restrict__ b_hh, const float* __restrict__ W_fc,
         const float* __restrict__ b_fc, float* __restrict__ out)
{
    extern __shared__ unsigned char smc[];
    const uint32_t sa = smem_u32(smc);
    const int tid = threadIdx.x, lane = tid & 31, w = tid >> 5;
    const int gb = blockIdx.x >> 5, ht = blockIdx.x & 31;
    const int wm = w & 1, wn = w >> 1;              // 2 M-tiles(32) x 4 N-tiles(16)
    float* bs = (float*)(smc + OFF_BIAS);

    // ---- W split -> SMEM: row n (= jj*4+gate), k-major, stride 1168B
    for (int idx = tid; idx < 64 * 576; idx += NTHR) {
        int k = idx >> 6, n = idx & 63;
        int row = (n & 3) * 512 + ht * 16 + (n >> 2);
        float v = (k < 512) ? W_hh[(size_t)row * 512 + k] : W_ih[(size_t)row * 64 + (k - 512)];
        unsigned short hi, lo;
        split1(v, hi, lo);
        *(unsigned short*)(smc + OFF_WHI + n * WSTRIDE + k * 2) = hi;
        *(unsigned short*)(smc + OFF_WLO + n * WSTRIDE + k * 2) = lo;
    }
    if (tid < 64) {
        int row = (tid & 3) * 512 + ht * 16 + (tid >> 2);
        bs[tid] = b_ih[row] + b_hh[row];
    }
    // zero h parity-0 for this CTA's (b,j) block
    if (tid < 128) {
        int r = tid >> 1, hh = tid & 1;
        uint4 z = make_uint4(0, 0, 0, 0);
        *(uint4*)(&g_hb[0][0][(size_t)(gb * 64 + r) * 512 + ht * 16 + hh * 8]) = z;
        *(uint4*)(&g_hb[0][1][(size_t)(gb * 64 + r) * 512 + ht * 16 + hh * 8]) = z;
    }

    // staging indices: 256 threads x 2 16B-units per plane
    const int sr = tid >> 2;                 // row 0..63
    const int su = (tid & 3) * 2;            // first 16B unit

    // issue one chunk (c==0 -> x(t); c>=1 -> h chunk c-1 of parity par) into ring buf c&3
    #define ISSUE(c, t, par) do {                                                      \
        uint32_t d0 = sa + OFF_A + (uint32_t)((c) & 3) * 16384u;                       \
        _Pragma("unroll")                                                              \
        for (int s2 = 0; s2 < 2; s2++) {                                               \
            int u = su + s2;                                                           \
            uint32_t dof = (uint32_t)sr * 128 +                                        \
                           (((uint32_t)u * 16) ^ ((uint32_t)(sr & 7) << 4));           \
            const unsigned short *shi, *slo;                                           \
            if ((c) == 0) {                                                            \
                size_t o = ((size_t)(gb * 64 + sr) * T_ + (t)) * 64 + u * 8;           \
                shi = &g_x2[0][o]; slo = &g_x2[1][o];                                  \
            } else {                                                                   \
                size_t o = (size_t)(gb * 64 + sr) * 512 + ((c) - 1) * 64 + u * 8;      \
                shi = &g_hb[par][0][o]; slo = &g_hb[par][1][o];                        \
            }                                                                          \
            cpa(d0 + dof, shi);                                                        \
            cpa(d0 + 8192 + dof, slo);                                                 \
        }                                                                              \
        cpa_commit();                                                                  \
    } while (0)

    // prefetch x(t=0) into buf0 (independent of h)
    ISSUE(0, 0, 0);
    gbar(gb);

    // per-lane address components (verified R5 mapping)
    const int rowl = lane & 15;
    const uint32_t xm = (uint32_t)(lane & 7) << 4;        // A swizzle mask
    const uint32_t kl = (uint32_t)(lane >> 4) * 16;       // A k-half (bytes)
    const int nloc = wn * 16 + (lane & 7) + ((lane >> 4) << 3);
    const uint32_t krel = (uint32_t)((lane >> 3) & 1) * 16;
    const uint32_t bBaseHi = sa + OFF_WHI + (uint32_t)nloc * WSTRIDE + krel;
    const uint32_t bBaseLo = sa + OFF_WLO + (uint32_t)nloc * WSTRIDE + krel;
    const uint32_t aRow0 = (uint32_t)(wm * 32 + rowl) * 128;

    const int q = lane & 3, mth = q & 1;
    float cst[4] = {0.f, 0.f, 0.f, 0.f};

    for (int t = 0; t < T_; t++) {
        const int par = t & 1, nb = par ^ 1;

        // post-barrier: start h chunks 1,2 (pending: x, h0, h1)
        ISSUE(1, t, par);
        ISSUE(2, t, par);

        float acc[2][2][4];
        #pragma unroll
        for (int a1 = 0; a1 < 2; a1++)
            #pragma unroll
            for (int a2 = 0; a2 < 2; a2++)
                #pragma unroll
                for (int a3 = 0; a3 < 4; a3++) acc[a1][a2][a3] = 0.f;

        for (int ch = 0; ch < 9; ch++) {
            if (ch == 7) cpa_wait1();
            else if (ch == 8) cpa_wait0();
            else cpa_wait2();                  // chunk ch landed; ch+1, ch+2 in flight
            __syncthreads();                   // visible to all; buf (ch-1) free
            if (ch <= 5) ISSUE(ch + 3, t, par);

            const uint32_t aB = sa + OFF_A + (uint32_t)(ch & 3) * 16384u;
            const uint32_t bK = (ch == 0) ? 1024u : (uint32_t)(ch - 1) * 128u;
            #pragma unroll
            for (int kt = 0; kt < 4; kt++) {
                uint32_t kq = (((uint32_t)kt * 32) + kl) ^ xm;
                uint32_t h0[4], h1[4], l0[4], l1[4], bh[4], bl[4];
                ldsm4(h0, aB + aRow0 + kq);
                ldsm4(h1, aB + aRow0 + 2048 + kq);
                ldsm4(l0, aB + 8192 + aRow0 + kq);
                ldsm4(l1, aB + 8192 + aRow0 + 2048 + kq);
                ldsm4(bh, bBaseHi + bK + kt * 32);
                ldsm4(bl, bBaseLo + bK + kt * 32);

                mma16816(acc[0][0], h0, bh[0], bh[1]);
                mma16816(acc[0][1], h0, bh[2], bh[3]);
                mma16816(acc[1][0], h1, bh[0], bh[1]);
                mma16816(acc[1][1], h1, bh[2], bh[3]);
                mma16816(acc[0][0], h0, bl[0], bl[1]);
                mma16816(acc[0][1], h0, bl[2], bl[3]);
                mma16816(acc[1][0], h1, bl[0], bl[1]);
                mma16816(acc[1][1], h1, bl[2], bl[3]);
                mma16816(acc[0][0], l0, bh[0], bh[1]);
                mma16816(acc[0][1], l0, bh[2], bh[3]);
                mma16816(acc[1][0], l1, bh[0], bh[1]);
                mma16816(acc[1][1], l1, bh[2], bh[3]);
            }
        }

        __syncthreads();       // all warps done reading buf0 (chunk 8)
        // prefetch next step's x into buf0 (overlaps epilogue + barrier)
        {
            int tn = (t + 1) & (T_ - 1);
            ISSUE(0, tn, par);
        }

        // ---- epilogue (verified R5 code): pair-exchange, gates, state update
        float recv[2][4];
        #pragma unroll
        for (int nt = 0; nt < 2; nt++)
            #pragma unroll
            for (int k2 = 0; k2 < 4; k2++) {
                float sv = mth ? acc[0][nt][k2] : acc[1][nt][k2];
                recv[nt][k2] = __shfl_xor_sync(0xffffffffu, sv, 1);
            }
        #pragma unroll
        for (int nt = 0; nt < 2; nt++) {
            int jj = wn * 4 + nt * 2 + (q >> 1);
            float bI = bs[jj * 4 + 0], bF = bs[jj * 4 + 1];
            float bG = bs[jj * 4 + 2], bO = bs[jj * 4 + 3];
            #pragma unroll
            for (int rh = 0; rh < 2; rh++) {
                float o0 = acc[mth][nt][rh * 2 + 0], o1 = acc[mth][nt][rh * 2 + 1];
                float r0 = recv[nt][rh * 2 + 0],     r1 = recv[nt][rh * 2 + 1];
                float I = (mth == 0 ? o0 : r0) + bI;
                float F = (mth == 0 ? o1 : r1) + bF;
                float G = (mth == 0 ? r0 : o0) + bG;
                float O = (mth == 0 ? r1 : o1) + bO;
                float iv = sigm(I), fv = sigm(F), gv = tanh_(G), ov = sigm(O);
                int ci = nt * 2 + rh;
                float cv = fv * cst[ci] + iv * gv;
                cst[ci] = cv;
                float ho = ov * tanh_(cv);
                int row = wm * 32 + mth * 16 + (lane >> 2) + rh * 8;
                int b = gb * 64 + row, j = ht * 16 + jj;
                unsigned short hi, lo;
                split1(ho, hi, lo);
                size_t o = (size_t)b * 512 + j;
                g_hb[nb][0][o] = hi;
                g_hb[nb][1][o] = lo;
                if (t == T_ - 1) g_hf[(size_t)j * 256 + b] = ho;
            }
        }
        gbar(gb);
    }

    // ================= FC head (verified R5 code) =================
    cpa_wait0();
    float* smf = (float*)smc;
    for (int idx = tid; idx < (H_ * 64) / 4; idx += NTHR) {
        int jj2 = idx >> 4, qv = idx & 15;
        *(float4*)(smf + jj2 * 64 + qv * 4) =
            __ldcg((const float4*)(g_hf + (size_t)jj2 * 256 + gb * 64 + qv * 4));
    }
    __syncthreads();

    const int tx2 = tid & 15, ty2 = tid >> 4;
    #pragma unroll
    for (int oi = 0; oi < 3; oi++) {
        int r = ht * 48 + ty2 * 3 + oi;
        const float4* wr = (const float4*)(W_fc + (size_t)r * H_);
        float a0, a1, a2, a3;
        a0 = a1 = a2 = a3 = b_fc[r];
        #pragma unroll 4
        for (int j4 = 0; j4 < H_ / 4; j4++) {
            float4 w4 = __ldg(wr + j4);
            float4 h0 = *(const float4*)(smf + (j4 * 4 + 0) * 64 + tx2 * 4);
            float4 h1 = *(const float4*)(smf + (j4 * 4 + 1) * 64 + tx2 * 4);
            float4 h2 = *(const float4*)(smf + (j4 * 4 + 2) * 64 + tx2 * 4);
            float4 h3 = *(const float4*)(smf + (j4 * 4 + 3) * 64 + tx2 * 4);
            a0 += h0.x * w4.x + h1.x * w4.y + h2.x * w4.z + h3.x * w4.w;
            a1 += h0.y * w4.x + h1.y * w4.y + h2.y * w4.z + h3.y * w4.w;
            a2 += h0.z * w4.x + h1.z * w4.y + h2.z * w4.z + h3.z * w4.w;
            a3 += h0.w * w4.x + h1.w * w4.y + h2.w * w4.z + h3.w * w4.w;
        }
        int bbase = gb * 64 + tx2 * 4;
        out[(size_t)(bbase + 0) * OUTC + r] = a0;
        out[(size_t)(bbase + 1) * OUTC + r] = a1;
        out[(size_t)(bbase + 2) * OUTC + r] = a2;
        out[(size_t)(bbase + 3) * OUTC + r] = a3;
    }
}

extern "C" void kernel_launch(void* const* d_in, const int* in_sizes, int n_in,
                              void* d_out, int out_size) {
    const float* x    = (const float*)d_in[0];
    const float* W_ih = (const float*)d_in[1];
    const float* W_hh = (const float*)d_in[2];
    const float* b_ih = (const float*)d_in[3];
    const float* b_hh = (const float*)d_in[4];
    const float* W_fc = (const float*)d_in[5];
    const float* b_fc = (const float*)d_in[6];
    float* out = (float*)d_out;

    xsplit<<<8192, 256>>>(x);
    cudaFuncSetAttribute(lstm_mma, cudaFuncAttributeMaxDynamicSharedMemorySize, SMEM_BYTES);
    lstm_mma<<<NCTA, NTHR, SMEM_BYTES>>>(x, W_ih, W_hh, b_ih, b_hh, W_fc, b_fc, out);
}

// round 8
// speedup vs baseline: 1.4646x; 1.0088x over previous
#include <cuda_runtime.h>
#include <cuda_bf16.h>
#include <cstdint>

#define B_   256
#define T_   512
#define H_   512
#define OUTC 1536

#define NCTA 256                // 4 batch groups x 64 N-tiles
#define NTHR 256

#define WSTRIDE 1168            // 576*2 + 16 pad -> ldmatrix conflict-free
#define OFF_WHI  0              // 32 x 1168
#define OFF_WLO  37376
#define OFF_A    74752          // 2 buffers x 16384 ([hi 8192 | lo 8192])
#define OFF_BIAS 107520         // 32 floats
#define SMEM_BYTES 107648       // fits 2 CTAs/SM (2x107.6K <= 228K)

// ---------------- persistent device scratch ----------------
__device__ unsigned short g_hb[2][2][B_ * H_];             // [parity][hi/lo][b*512+j]
__device__ unsigned short g_x2[2][(size_t)B_ * T_ * 64];   // [hi/lo][b][t][f]
__device__ float g_hf[H_ * B_];                            // final h, [j*256+b]
__device__ unsigned g_cnt[4 * 32];
__device__ volatile unsigned g_gen[4 * 32];

// ---------------- helpers ----------------
__device__ __forceinline__ uint32_t smem_u32(const void* p) {
    uint32_t a;
    asm("{ .reg .u64 t; cvta.to.shared.u64 t, %1; cvt.u32.u64 %0, t; }" : "=r"(a) : "l"(p));
    return a;
}
__device__ __forceinline__ void split1(float v, unsigned short& hi, unsigned short& lo) {
    __nv_bfloat16 h = __float2bfloat16_rn(v);
    float rem = v - __bfloat162float(h);
    hi = __bfloat16_as_ushort(h);
    lo = __bfloat16_as_ushort(__float2bfloat16_rn(rem));
}
__device__ __forceinline__ float sigm(float x) {
    return __fdividef(1.0f, 1.0f + __expf(-x));
}
__device__ __forceinline__ float tanh_(float x) {
    float e = __expf(2.0f * x);
    return 1.0f - __fdividef(2.0f, e + 1.0f);
}
__device__ __forceinline__ void cpa(uint32_t dst, const void* src) {
    asm volatile("cp.async.cg.shared.global [%0], [%1], 16;" :: "r"(dst), "l"(src) : "memory");
}
__device__ __forceinline__ void cpa_commit() { asm volatile("cp.async.commit_group;" ::: "memory"); }
__device__ __forceinline__ void cpa_wait0()  { asm volatile("cp.async.wait_group 0;" ::: "memory"); }

__device__ __forceinline__ void ldsm4(uint32_t* r, uint32_t a) {
    asm volatile("ldmatrix.sync.aligned.m8n8.x4.shared.b16 {%0,%1,%2,%3}, [%4];"
                 : "=r"(r[0]), "=r"(r[1]), "=r"(r[2]), "=r"(r[3]) : "r"(a));
}
__device__ __forceinline__ void mma16816(float* c, const uint32_t* a, uint32_t b0, uint32_t b1) {
    asm volatile(
        "mma.sync.aligned.m16n8k16.row.col.f32.bf16.bf16.f32 "
        "{%0,%1,%2,%3}, {%4,%5,%6,%7}, {%8,%9}, {%0,%1,%2,%3};"
        : "+f"(c[0]), "+f"(c[1]), "+f"(c[2]), "+f"(c[3])
        : "r"(a[0]), "r"(a[1]), "r"(a[2]), "r"(a[3]), "r"(b0), "r"(b1));
}

// group barrier across the 64 CTAs of one batch group
__device__ __forceinline__ void gbar(int gb) {
    __threadfence();
    __syncthreads();
    if (threadIdx.x == 0) {
        volatile unsigned* gp = &g_gen[gb * 32];
        unsigned g = *gp;
        if (atomicAdd(&g_cnt[gb * 32], 1u) == 63u) {
            atomicExch(&g_cnt[gb * 32], 0u);
            __threadfence();
            *gp = g + 1u;
        } else {
            while (*gp == g) { }
        }
        __threadfence();
    }
    __syncthreads();
}

// ============ x prep: fp32 -> split bf16 (same [b][t][f] layout) ============
extern "C" __global__ void xsplit(const float* __restrict__ x) {
    size_t i = ((size_t)blockIdx.x * 256 + threadIdx.x) * 4;
    float4 v = __ldg((const float4*)(x + i));
    unsigned short h0, l0, h1, l1, h2, l2, h3, l3;
    split1(v.x, h0, l0); split1(v.y, h1, l1);
    split1(v.z, h2, l2); split1(v.w, h3, l3);
    ushort4 H = {h0, h1, h2, h3}, L = {l0, l1, l2, l3};
    *(ushort4*)(&g_x2[0][i]) = H;
    *(ushort4*)(&g_x2[1][i]) = L;
}

// ============ main persistent kernel ============
extern "C" __global__ void __launch_bounds__(NTHR, 2)
lstm_mma(const float* __restrict__ x,    const float* __restrict__ W_ih,
         const float* __restrict__ W_hh, const float* __restrict__ b_ih,
         const float* __restrict__ b_hh, const float* __restrict__ W_fc,
         const float* __restrict__ b_fc, float* __restrict__ out)
{
    extern __shared__ unsigned char smc[];
    const uint32_t sa = smem_u32(smc);
    const int tid = threadIdx.x, lane = tid & 31, w = tid >> 5;
    const int gb = blockIdx.x >> 6, ht = blockIdx.x & 63;   // 4 groups x 64 tiles
    const int wm = w & 3, wn = w >> 2;                      // 4 M-tiles(16) x 2 N-tiles(16)
    float* bs = (float*)(smc + OFF_BIAS);

    // ---- W split -> SMEM: 32 rows (n = jj*4+gate, jj 0..7), k-major, stride 1168B
    for (int idx = tid; idx < 32 * 576; idx += NTHR) {
        int k = idx >> 5, n = idx & 31;
        int row = (n & 3) * 512 + ht * 8 + (n >> 2);
        float v = (k < 512) ? W_hh[(size_t)row * 512 + k] : W_ih[(size_t)row * 64 + (k - 512)];
        unsigned short hi, lo;
        split1(v, hi, lo);
        *(unsigned short*)(smc + OFF_WHI + n * WSTRIDE + k * 2) = hi;
        *(unsigned short*)(smc + OFF_WLO + n * WSTRIDE + k * 2) = lo;
    }
    if (tid < 32) {
        int row = (tid & 3) * 512 + ht * 8 + (tid >> 2);
        bs[tid] = b_ih[row] + b_hh[row];
    }
    // zero h parity-0 for this CTA's (b, j) block: 64 b x 8 j x 2 planes
    if (tid < 128) {
        int r = tid >> 1, pl = tid & 1;
        uint4 z = make_uint4(0, 0, 0, 0);
        *(uint4*)(&g_hb[0][pl][(size_t)(gb * 64 + r) * 512 + ht * 8]) = z;
    }

    // staging indices: 256 threads x 2 16B-units per plane (64 rows x 128B)
    const int sr = tid >> 2;
    const int su = (tid & 3) * 2;

    // issue chunk (c==0 -> x(t); c>=1 -> h chunk c-1) into buffer c&1
    #define ISSUE(c, t, par) do {                                                      \
        uint32_t d0 = sa + OFF_A + (uint32_t)((c) & 1) * 16384u;                       \
        _Pragma("unroll")                                                              \
        for (int s2 = 0; s2 < 2; s2++) {                                               \
            int u = su + s2;                                                           \
            uint32_t dof = (uint32_t)sr * 128 +                                        \
                           (((uint32_t)u * 16) ^ ((uint32_t)(sr & 7) << 4));           \
            const unsigned short *shi, *slo;                                           \
            if ((c) == 0) {                                                            \
                size_t o = ((size_t)(gb * 64 + sr) * T_ + (t)) * 64 + u * 8;           \
                shi = &g_x2[0][o]; slo = &g_x2[1][o];                                  \
            } else {                                                                   \
                size_t o = (size_t)(gb * 64 + sr) * 512 + ((c) - 1) * 64 + u * 8;      \
                shi = &g_hb[par][0][o]; slo = &g_hb[par][1][o];                        \
            }                                                                          \
            cpa(d0 + dof, shi);                                                        \
            cpa(d0 + 8192 + dof, slo);                                                 \
        }                                                                              \
        cpa_commit();                                                                  \
    } while (0)

    // prefetch x(t=0) into buf0 (independent of h)
    ISSUE(0, 0, 0);
    gbar(gb);

    // per-lane address components (verified R6 16x16 mapping)
    const int rowl = lane & 15;
    const uint32_t xm = (uint32_t)(lane & 7) << 4;
    const uint32_t kl = (uint32_t)(lane >> 4) * 16;
    const int nloc = wn * 16 + (lane & 7) + ((lane >> 4) << 3);
    const uint32_t krel = (uint32_t)((lane >> 3) & 1) * 16;
    const uint32_t bBaseHi = sa + OFF_WHI + (uint32_t)nloc * WSTRIDE + krel;
    const uint32_t bBaseLo = sa + OFF_WLO + (uint32_t)nloc * WSTRIDE + krel;
    const uint32_t aRow0 = (uint32_t)(wm * 16 + rowl) * 128;

    const int q = lane & 3, mth = q & 1;
    float cst[2] = {0.f, 0.f};

    for (int t = 0; t < T_; t++) {
        const int par = t & 1, nb = par ^ 1;

        float accm[2][4], accc[2][4];
        #pragma unroll
        for (int hf = 0; hf < 2; hf++)
            #pragma unroll
            for (int k2 = 0; k2 < 4; k2++) { accm[hf][k2] = 0.f; accc[hf][k2] = 0.f; }

        // chunk 0 = x (W k-offset 1024B); chunks 1..8 = h 0..7
        for (int ch = 0; ch < 9; ch++) {
            cpa_wait0();               // chunk ch landed
            __syncthreads();           // all warps done with buffer being re-issued
            if (ch < 8) ISSUE(ch + 1, t, par);

            const uint32_t aB = sa + OFF_A + (uint32_t)(ch & 1) * 16384u;
            const uint32_t bK = (ch == 0) ? 1024u : (uint32_t)(ch - 1) * 128u;
            #pragma unroll
            for (int kt = 0; kt < 4; kt++) {
                uint32_t kq = (((uint32_t)kt * 32) + kl) ^ xm;
                uint32_t hi[4], lo[4], bh[4], bl[4];
                ldsm4(hi, aB + aRow0 + kq);
                ldsm4(lo, aB + 8192 + aRow0 + kq);
                ldsm4(bh, bBaseHi + bK + kt * 32);
                ldsm4(bl, bBaseLo + bK + kt * 32);
                mma16816(accm[0], hi, bh[0], bh[1]);
                mma16816(accm[1], hi, bh[2], bh[3]);
                mma16816(accc[0], hi, bl[0], bl[1]);
                mma16816(accc[1], hi, bl[2], bl[3]);
                mma16816(accc[0], lo, bh[0], bh[1]);
                mma16816(accc[1], lo, bh[2], bh[3]);
            }
        }

        __syncthreads();       // all warps done reading buf0 (chunk 8)
        { int tn = (t + 1) & (T_ - 1); ISSUE(0, tn, par); }   // next x overlaps epilogue+barrier

        // ---- epilogue (verified R6 code): pair-exchange, gates, state update
        float cmb[2][4];
        #pragma unroll
        for (int hf = 0; hf < 2; hf++)
            #pragma unroll
            for (int k2 = 0; k2 < 4; k2++) cmb[hf][k2] = accm[hf][k2] + accc[hf][k2];

        float recv[2][2];
        #pragma unroll
        for (int hf = 0; hf < 2; hf++) {
            float s0 = mth ? cmb[hf][0] : cmb[hf][2];
            float s1 = mth ? cmb[hf][1] : cmb[hf][3];
            recv[hf][0] = __shfl_xor_sync(0xffffffffu, s0, 1);
            recv[hf][1] = __shfl_xor_sync(0xffffffffu, s1, 1);
        }
        const int rown = wm * 16 + (lane >> 2) + mth * 8;
        const int b = gb * 64 + rown;
        #pragma unroll
        for (int hf = 0; hf < 2; hf++) {
            int jj = wn * 4 + (q >> 1) + hf * 2;
            float I, F, G, O;
            if (mth == 0) { I = cmb[hf][0]; F = cmb[hf][1]; G = recv[hf][0]; O = recv[hf][1]; }
            else          { G = cmb[hf][2]; O = cmb[hf][3]; I = recv[hf][0]; F = recv[hf][1]; }
            I += bs[jj * 4 + 0]; F += bs[jj * 4 + 1];
            G += bs[jj * 4 + 2]; O += bs[jj * 4 + 3];
            float iv = sigm(I), fv = sigm(F), gv = tanh_(G), ov = sigm(O);
            float cv = fv * cst[hf] + iv * gv;
            cst[hf] = cv;
            float ho = ov * tanh_(cv);
            unsigned short hi, lo;
            split1(ho, hi, lo);
            int j = ht * 8 + jj;
            size_t o = (size_t)b * 512 + j;
            g_hb[nb][0][o] = hi;
            g_hb[nb][1][o] = lo;
            if (t == T_ - 1) g_hf[(size_t)j * 256 + b] = ho;
        }
        gbar(gb);
    }

    // ================= FC head (h read from L2; tiny tail) =================
    cpa_wait0();
    const int tx2 = tid & 15, ty2 = tid >> 4;
    #pragma unroll
    for (int oi = 0; oi < 2; oi++) {
        int rl = oi * 16 + ty2;
        if (rl < 24) {
            int r = ht * 24 + rl;
            const float4* wr = (const float4*)(W_fc + (size_t)r * H_);
            float a0, a1, a2, a3;
            a0 = a1 = a2 = a3 = b_fc[r];
            #pragma unroll 4
            for (int j4 = 0; j4 < H_ / 4; j4++) {
                float4 w4 = __ldg(wr + j4);
                float4 h0 = __ldg((const float4*)(g_hf + (size_t)(j4 * 4 + 0) * 256 + gb * 64 + tx2 * 4));
                float4 h1 = __ldg((const float4*)(g_hf + (size_t)(j4 * 4 + 1) * 256 + gb * 64 + tx2 * 4));
                float4 h2 = __ldg((const float4*)(g_hf + (size_t)(j4 * 4 + 2) * 256 + gb * 64 + tx2 * 4));
                float4 h3 = __ldg((const float4*)(g_hf + (size_t)(j4 * 4 + 3) * 256 + gb * 64 + tx2 * 4));
                a0 += h0.x * w4.x + h1.x * w4.y + h2.x * w4.z + h3.x * w4.w;
                a1 += h0.y * w4.x + h1.y * w4.y + h2.y * w4.z + h3.y * w4.w;
                a2 += h0.z * w4.x + h1.z * w4.y + h2.z * w4.z + h3.z * w4.w;
                a3 += h0.w * w4.x + h1.w * w4.y + h2.w * w4.z + h3.w * w4.w;
            }
            int bbase = gb * 64 + tx2 * 4;
            out[(size_t)(bbase + 0) * OUTC + r] = a0;
            out[(size_t)(bbase + 1) * OUTC + r] = a1;
            out[(size_t)(bbase + 2) * OUTC + r] = a2;
            out[(size_t)(bbase + 3) * OUTC + r] = a3;
        }
    }
}

extern "C" void kernel_launch(void* const* d_in, const int* in_sizes, int n_in,
                              void* d_out, int out_size) {
    const float* x    = (const float*)d_in[0];
    const float* W_ih = (const float*)d_in[1];
    const float* W_hh = (const float*)d_in[2];
    const float* b_ih = (const float*)d_in[3];
    const float* b_hh = (const float*)d_in[4];
    const float* W_fc = (const float*)d_in[5];
    const float* b_fc = (const float*)d_in[6];
    float* out = (float*)d_out;

    xsplit<<<8192, 256>>>(x);
    cudaFuncSetAttribute(lstm_mma, cudaFuncAttributeMaxDynamicSharedMemorySize, SMEM_BYTES);
    lstm_mma<<<NCTA, NTHR, SMEM_BYTES>>>(x, W_ih, W_hh, b_ih, b_hh, W_fc, b_fc, out);
}